// round 2
// baseline (speedup 1.0000x reference)
#include <cuda_runtime.h>

// VectorQuantizer: z (32,64,32,32) f32, codebook (1024,64) f32.
// Output: z_quantized (32,64,32,32) followed by scalar loss.
//
// Matches the reference's fp32 rounding: dist_k = fl(fl(z2 - 2*dot_k) + cn_k),
// argmin with strict-< (first index wins, like jnp.argmin on the quantized
// values). Straight-through output is the two-step fl(z + fl(q - z)).

#define NUM_CODES 1024
#define DIM       64
#define HW        1024            // 32*32
#define N_VEC     32768           // 32*32*32 vectors
#define N_TOTAL   2097152         // 32*64*32*32 elements
#define TPB       128
#define NBLOCKS   256             // TPB*NBLOCKS == N_VEC
#define CHUNK     128             // codes per smem chunk (32 KB)

__device__ float g_cnorm[NUM_CODES];
__device__ float g_partial[NBLOCKS];

// ---------------------------------------------------------------------------
// Kernel 0: codebook row norms ||c_k||^2 (order-insensitive: cn ~ 2e-5,
// its ulp is far below the comparison grid at |z|^2 ~ 64).
// ---------------------------------------------------------------------------
__global__ void cnorm_kernel(const float* __restrict__ cb) {
    int k = blockIdx.x * blockDim.x + threadIdx.x;
    if (k < NUM_CODES) {
        const float4* row = (const float4*)(cb + (size_t)k * DIM);
        float s = 0.0f;
#pragma unroll
        for (int i = 0; i < DIM / 4; i++) {
            float4 v = row[i];
            s = fmaf(v.x, v.x, s);
            s = fmaf(v.y, v.y, s);
            s = fmaf(v.z, v.z, s);
            s = fmaf(v.w, v.w, s);
        }
        g_cnorm[k] = s;
    }
}

// ---------------------------------------------------------------------------
// Kernel 1: main VQ — argmin + gather + output + loss partials
// ---------------------------------------------------------------------------
__global__ void __launch_bounds__(TPB, 2)
vq_main_kernel(const float* __restrict__ z,
               const float* __restrict__ cb,
               float* __restrict__ out) {
    __shared__ __align__(16) float s_cb[CHUNK][DIM];   // 32 KB
    __shared__ float s_cn[CHUNK];
    __shared__ float s_red[TPB];

    const int tid = threadIdx.x;
    const int n   = blockIdx.x * TPB + tid;            // vector id, < N_VEC
    const int b   = n >> 10;                           // batch
    const int hw  = n & (HW - 1);                      // h*32+w

    // Load this thread's z vector: element c lives at z[b, c, h, w],
    // stride HW floats in c. Coalesced across the warp (consecutive hw).
    const float* zp = z + (size_t)b * DIM * HW + hw;
    float zreg[DIM];
#pragma unroll
    for (int c = 0; c < DIM; c++) zreg[c] = zp[(size_t)c * HW];

    // ||z||^2 in fp32. Exact order vs the reference does not matter: any
    // fp32 value in the same binade shifts ALL quantized dists by the same
    // grid multiple, leaving argmin + ties invariant.
    float zn = 0.0f;
#pragma unroll
    for (int c = 0; c < DIM; c++) zn = fmaf(zreg[c], zreg[c], zn);

    float best  = 3.402823466e38f;
    int   bestk = 0;

    for (int k0 = 0; k0 < NUM_CODES; k0 += CHUNK) {
        __syncthreads();  // protect smem before overwrite
        // Cooperative chunk load: 128 codes x 64 floats (float4, coalesced)
        const float4* src = (const float4*)(cb + (size_t)k0 * DIM);
        float4* dst = (float4*)&s_cb[0][0];
#pragma unroll
        for (int i = tid; i < CHUNK * DIM / 4; i += TPB) dst[i] = src[i];
        if (tid < CHUNK) s_cn[tid] = g_cnorm[k0 + tid];
        __syncthreads();

#pragma unroll 1
        for (int k = 0; k < CHUNK; k += 4) {
            float d0 = 0.f, d1 = 0.f, d2 = 0.f, d3 = 0.f;
            const float4* r0 = (const float4*)s_cb[k + 0];
            const float4* r1 = (const float4*)s_cb[k + 1];
            const float4* r2 = (const float4*)s_cb[k + 2];
            const float4* r3 = (const float4*)s_cb[k + 3];
#pragma unroll
            for (int i = 0; i < DIM / 4; i++) {
                float4 a0 = r0[i], a1 = r1[i], a2 = r2[i], a3 = r3[i];
                float z0 = zreg[4 * i + 0], z1 = zreg[4 * i + 1];
                float z2 = zreg[4 * i + 2], z3 = zreg[4 * i + 3];
                d0 = fmaf(a0.x, z0, d0); d0 = fmaf(a0.y, z1, d0);
                d0 = fmaf(a0.z, z2, d0); d0 = fmaf(a0.w, z3, d0);
                d1 = fmaf(a1.x, z0, d1); d1 = fmaf(a1.y, z1, d1);
                d1 = fmaf(a1.z, z2, d1); d1 = fmaf(a1.w, z3, d1);
                d2 = fmaf(a2.x, z0, d2); d2 = fmaf(a2.y, z1, d2);
                d2 = fmaf(a2.z, z2, d2); d2 = fmaf(a2.w, z3, d2);
                d3 = fmaf(a3.x, z0, d3); d3 = fmaf(a3.y, z1, d3);
                d3 = fmaf(a3.z, z2, d3); d3 = fmaf(a3.w, z3, d3);
            }
            // Reference combine, with its exact fp32 rounding sequence:
            //   dist = fl( fl( z2 - fl(2*dot) ) + cn )
            // Intrinsics prevent FMA contraction / reassociation.
            float s0 = __fadd_rn(__fsub_rn(zn, __fmul_rn(2.0f, d0)), s_cn[k + 0]);
            float s1 = __fadd_rn(__fsub_rn(zn, __fmul_rn(2.0f, d1)), s_cn[k + 1]);
            float s2 = __fadd_rn(__fsub_rn(zn, __fmul_rn(2.0f, d2)), s_cn[k + 2]);
            float s3 = __fadd_rn(__fsub_rn(zn, __fmul_rn(2.0f, d3)), s_cn[k + 3]);
            // Strict < keeps the FIRST min (jnp.argmin tie-break).
            if (s0 < best) { best = s0; bestk = k0 + k + 0; }
            if (s1 < best) { best = s1; bestk = k0 + k + 1; }
            if (s2 < best) { best = s2; bestk = k0 + k + 2; }
            if (s3 < best) { best = s3; bestk = k0 + k + 3; }
        }
    }

    // Gather winning code (L2-resident), write output, accumulate loss.
    const float* crow = cb + (size_t)bestk * DIM;
    float* op = out + (size_t)b * DIM * HW + hw;
    float lsum = 0.0f;
#pragma unroll
    for (int c = 0; c < DIM; c++) {
        float q = crow[c];
        float d = __fsub_rn(q, zreg[c]);       // fl(q - z), as in reference
        lsum = fmaf(d, d, lsum);
        op[(size_t)c * HW] = __fadd_rn(zreg[c], d);  // fl(z + fl(q - z))
    }

    // Deterministic block reduction of the loss partial.
    __syncthreads();
    s_red[tid] = lsum;
    __syncthreads();
#pragma unroll
    for (int s = TPB / 2; s > 0; s >>= 1) {
        if (tid < s) s_red[tid] += s_red[tid + s];
        __syncthreads();
    }
    if (tid == 0) g_partial[blockIdx.x] = s_red[0];
}

// ---------------------------------------------------------------------------
// Kernel 2: final loss reduction (deterministic, fixed order)
// ---------------------------------------------------------------------------
__global__ void loss_kernel(float* __restrict__ loss_out) {
    __shared__ float s_red[NBLOCKS];
    int tid = threadIdx.x;
    s_red[tid] = g_partial[tid];
    __syncthreads();
#pragma unroll
    for (int s = NBLOCKS / 2; s > 0; s >>= 1) {
        if (tid < s) s_red[tid] += s_red[tid + s];
        __syncthreads();
    }
    if (tid == 0) {
        // loss = mean(d^2) + 0.25*mean(d^2) = 1.25 * sum / N_TOTAL
        loss_out[0] = s_red[0] * (1.25f / (float)N_TOTAL);
    }
}

// ---------------------------------------------------------------------------
extern "C" void kernel_launch(void* const* d_in, const int* in_sizes, int n_in,
                              void* d_out, int out_size) {
    const float* z  = (const float*)d_in[0];
    const float* cb = (const float*)d_in[1];
    float* out = (float*)d_out;

    cnorm_kernel<<<(NUM_CODES + 255) / 256, 256>>>(cb);
    vq_main_kernel<<<NBLOCKS, TPB>>>(z, cb, out);
    if (out_size > N_TOTAL) {
        // scalar loss lives at the tail of the output buffer
        loss_kernel<<<1, NBLOCKS>>>(out + (out_size - 1));
    }
}

// round 3
// speedup vs baseline: 1.0720x; 1.0720x over previous
#include <cuda_runtime.h>

// VectorQuantizer: z (32,64,32,32) f32, codebook (1024,64) f32.
// Output: z_quantized (32,64,32,32) followed by scalar loss.
//
// Round 3: packed fma.rn.f32x2 (FFMA2) — two CODES per instruction, each
// lane keeping the exact sequential per-dim fmaf order of the round-2
// passing kernel, so dots/scores/argmin are bit-identical to it.

#define NUM_CODES 1024
#define DIM       64
#define HW        1024            // 32*32
#define N_VEC     32768           // 32*32*32 vectors
#define N_TOTAL   2097152         // 32*64*32*32 elements
#define TPB       128
#define NBLOCKS   256             // TPB*NBLOCKS == N_VEC
#define CHUNK     128             // codes per smem chunk (32 KB)

__device__ float g_cnorm[NUM_CODES];
__device__ float g_partial[NBLOCKS];

// ---- f32x2 helpers -------------------------------------------------------
__device__ __forceinline__ unsigned long long ffma2(unsigned long long a,
                                                    unsigned long long b,
                                                    unsigned long long c) {
    unsigned long long d;
    asm("fma.rn.f32x2 %0, %1, %2, %3;" : "=l"(d) : "l"(a), "l"(b), "l"(c));
    return d;
}
__device__ __forceinline__ unsigned long long pack2(float lo, float hi) {
    unsigned long long d;
    asm("mov.b64 %0, {%1, %2};" : "=l"(d) : "f"(lo), "f"(hi));
    return d;
}
__device__ __forceinline__ void unpack2(unsigned long long v, float& lo, float& hi) {
    asm("mov.b64 {%0, %1}, %2;" : "=f"(lo), "=f"(hi) : "l"(v));
}

// ---------------------------------------------------------------------------
// Kernel 0: codebook row norms, one warp per code (shuffle reduction).
// cn ~ 2e-5; order-change perturbation ~1e-12 is far below the fp32 grid
// of the |z|^2 ~ 64 comparison values -> argmin-safe.
// ---------------------------------------------------------------------------
__global__ void cnorm_kernel(const float* __restrict__ cb) {
    int w = (blockIdx.x * blockDim.x + threadIdx.x) >> 5;   // code id
    int l = threadIdx.x & 31;
    if (w < NUM_CODES) {
        float2 v = *(const float2*)(cb + (size_t)w * DIM + 2 * l);
        float s = fmaf(v.x, v.x, v.y * v.y);
#pragma unroll
        for (int off = 16; off > 0; off >>= 1)
            s += __shfl_down_sync(0xFFFFFFFFu, s, off);
        if (l == 0) g_cnorm[w] = s;
    }
}

// ---------------------------------------------------------------------------
// Kernel 1: main VQ — argmin + gather + output + loss partials
// ---------------------------------------------------------------------------
__global__ void __launch_bounds__(TPB, 2)
vq_main_kernel(const float* __restrict__ z,
               const float* __restrict__ cb,
               float* __restrict__ out) {
    // Code-pair interleaved chunk: s_cb[pair p][dim i][parity] ->
    // float at offset p*128 + i*2 + par. One ulonglong2 (16B) read at
    // (p*128 + 4i) gives {c_even[2i],c_odd[2i]} , {c_even[2i+1],c_odd[2i+1]}.
    __shared__ __align__(16) float s_cb[CHUNK * DIM];   // 32 KB
    __shared__ float s_cn[CHUNK];
    __shared__ float s_red[TPB];

    const int tid = threadIdx.x;
    const int n   = blockIdx.x * TPB + tid;            // vector id
    const int b   = n >> 10;                           // batch
    const int hw  = n & (HW - 1);                      // h*32+w

    // Load z vector (stride HW in channel; coalesced across warp) and
    // duplicate each element into a {z,z} 64-bit pair for FFMA2.
    const float* zp = z + (size_t)b * DIM * HW + hw;
    unsigned long long zz[DIM];
    float zn = 0.0f;
#pragma unroll
    for (int c = 0; c < DIM; c++) {
        float v = zp[(size_t)c * HW];
        zn = fmaf(v, v, zn);          // same sequential order as round 2
        zz[c] = pack2(v, v);
    }

    float best  = 3.402823466e38f;
    int   bestk = 0;

#pragma unroll 1
    for (int k0 = 0; k0 < NUM_CODES; k0 += CHUNK) {
        __syncthreads();  // protect smem before overwrite
        // Cooperative interleaving store: code k element i -> [k>>1][i][k&1]
        const float4* src = (const float4*)(cb + (size_t)k0 * DIM);
#pragma unroll
        for (int j = tid; j < CHUNK * DIM / 4; j += TPB) {
            float4 v = src[j];
            int k  = j >> 4;               // code within chunk
            int i0 = (j & 15) << 2;        // first dim of this float4
            float* base = s_cb + (k >> 1) * (2 * DIM) + (k & 1);
            base[(i0 + 0) * 2] = v.x;
            base[(i0 + 1) * 2] = v.y;
            base[(i0 + 2) * 2] = v.z;
            base[(i0 + 3) * 2] = v.w;
        }
        if (tid < CHUNK) s_cn[tid] = g_cnorm[k0 + tid];
        __syncthreads();

#pragma unroll 1
        for (int k = 0; k < CHUNK; k += 4) {
            // pair 0 = codes (k, k+1), pair 1 = codes (k+2, k+3)
            const ulonglong2* r0 =
                (const ulonglong2*)(s_cb + (k >> 1) * (2 * DIM));
            const ulonglong2* r1 =
                (const ulonglong2*)(s_cb + (k >> 1) * (2 * DIM) + 2 * DIM);
            unsigned long long acc0 = 0ULL, acc1 = 0ULL;   // {0.f, 0.f}
#pragma unroll
            for (int i = 0; i < DIM / 2; i++) {
                ulonglong2 a = r0[i];      // dims 2i, 2i+1 of codes k,k+1
                ulonglong2 c = r1[i];      // dims 2i, 2i+1 of codes k+2,k+3
                acc0 = ffma2(a.x, zz[2 * i], acc0);
                acc1 = ffma2(c.x, zz[2 * i], acc1);
                acc0 = ffma2(a.y, zz[2 * i + 1], acc0);
                acc1 = ffma2(c.y, zz[2 * i + 1], acc1);
            }
            float d0, d1, d2, d3;
            unpack2(acc0, d0, d1);
            unpack2(acc1, d2, d3);
            // Reference combine with its exact fp32 rounding sequence:
            //   dist = fl( fl( zn - fl(2*dot) ) + cn )
            float s0 = __fadd_rn(__fsub_rn(zn, __fmul_rn(2.0f, d0)), s_cn[k + 0]);
            float s1 = __fadd_rn(__fsub_rn(zn, __fmul_rn(2.0f, d1)), s_cn[k + 1]);
            float s2 = __fadd_rn(__fsub_rn(zn, __fmul_rn(2.0f, d2)), s_cn[k + 2]);
            float s3 = __fadd_rn(__fsub_rn(zn, __fmul_rn(2.0f, d3)), s_cn[k + 3]);
            // Strict < keeps the FIRST min (jnp.argmin tie-break).
            if (s0 < best) { best = s0; bestk = k0 + k + 0; }
            if (s1 < best) { best = s1; bestk = k0 + k + 1; }
            if (s2 < best) { best = s2; bestk = k0 + k + 2; }
            if (s3 < best) { best = s3; bestk = k0 + k + 3; }
        }
    }

    // Gather winning code (L2-resident), write output, accumulate loss.
    const float* crow = cb + (size_t)bestk * DIM;
    float* op = out + (size_t)b * DIM * HW + hw;
    float lsum = 0.0f;
#pragma unroll
    for (int c = 0; c < DIM; c++) {
        float q = crow[c];
        float zv, dummy;
        unpack2(zz[c], zv, dummy);
        float d = __fsub_rn(q, zv);            // fl(q - z)
        lsum = fmaf(d, d, lsum);
        op[(size_t)c * HW] = __fadd_rn(zv, d); // fl(z + fl(q - z))
    }

    // Deterministic block reduction of the loss partial.
    __syncthreads();
    s_red[tid] = lsum;
    __syncthreads();
#pragma unroll
    for (int s = TPB / 2; s > 0; s >>= 1) {
        if (tid < s) s_red[tid] += s_red[tid + s];
        __syncthreads();
    }
    if (tid == 0) g_partial[blockIdx.x] = s_red[0];
}

// ---------------------------------------------------------------------------
// Kernel 2: final loss reduction (deterministic, fixed order)
// ---------------------------------------------------------------------------
__global__ void loss_kernel(float* __restrict__ loss_out) {
    __shared__ float s_red[NBLOCKS];
    int tid = threadIdx.x;
    s_red[tid] = g_partial[tid];
    __syncthreads();
#pragma unroll
    for (int s = NBLOCKS / 2; s > 0; s >>= 1) {
        if (tid < s) s_red[tid] += s_red[tid + s];
        __syncthreads();
    }
    if (tid == 0) {
        // loss = mean(d^2) + 0.25*mean(d^2) = 1.25 * sum / N_TOTAL
        loss_out[0] = s_red[0] * (1.25f / (float)N_TOTAL);
    }
}

// ---------------------------------------------------------------------------
extern "C" void kernel_launch(void* const* d_in, const int* in_sizes, int n_in,
                              void* d_out, int out_size) {
    const float* z  = (const float*)d_in[0];
    const float* cb = (const float*)d_in[1];
    float* out = (float*)d_out;

    cnorm_kernel<<<NUM_CODES * 32 / 256, 256>>>(cb);
    vq_main_kernel<<<NBLOCKS, TPB>>>(z, cb, out);
    if (out_size > N_TOTAL) {
        loss_kernel<<<1, NBLOCKS>>>(out + (out_size - 1));
    }
}

// round 5
// speedup vs baseline: 1.7156x; 1.6003x over previous
#include <cuda_runtime.h>
#include <cstdint>

// VectorQuantizer: tf32 mma.sync filter + exact fp32 recheck.
// z (32,64,32,32) f32, codebook (1024,64) f32.
// Output: z_quantized (2097152 f32) + scalar loss at tail.

#define NUM_CODES 1024
#define DIM       64
#define HW        1024
#define N_VEC     32768
#define N_TOTAL   2097152
#define TPB       128
#define NBLOCKS   256
#define NCHUNK    16          // 16 chunks x 64 codes
#define EPS2      1.5e-3f     // 2.1x worst-case tf32 score-error bound
#define MAXCAND   32
#define DPAD      68          // D row stride (f32): 16B-aligned, conflict-free

// dynamic smem layout (bytes)
#define OFF_B     0           // 2 x 4096 u32   = 32768
#define OFF_D     32768       // 4 w x 32 x 68  = 34816
#define OFF_CN    67584       // 1024 f32       = 4096
#define OFF_RED   71680       // 128 f32        = 512
#define SMEM_TOTAL 72192

__device__ float    g_cnorm[NUM_CODES];
__device__ float    g_partial[NBLOCKS];
__device__ uint32_t g_bfrag[NUM_CODES * DIM];   // 256 KB, fragment-ordered tf32
__device__ uint32_t g_afrag[N_VEC * DIM];       // 8 MB,  fragment-ordered tf32

__device__ __forceinline__ uint32_t f2tf32(float f) {
    uint32_t u; asm("cvt.rna.tf32.f32 %0, %1;" : "=r"(u) : "f"(f)); return u;
}
// m16n8k8 row.col tf32: A 4 regs, B 2 regs, D 4 f32 (accumulate in place)
__device__ __forceinline__ void mma_tf32(float* d, const uint32_t* a,
                                         uint32_t b0, uint32_t b1) {
    asm("mma.sync.aligned.m16n8k8.row.col.f32.tf32.tf32.f32 "
        "{%0,%1,%2,%3}, {%4,%5,%6,%7}, {%8,%9}, {%0,%1,%2,%3};"
        : "+f"(d[0]), "+f"(d[1]), "+f"(d[2]), "+f"(d[3])
        : "r"(a[0]), "r"(a[1]), "r"(a[2]), "r"(a[3]), "r"(b0), "r"(b1));
}

// exact fp32 score, byte-identical to the round-2 passing kernel
__device__ __forceinline__ float exact_score(const float* __restrict__ cb, int k,
                                             const float* zr, float zn, float cn) {
    const float4* row = (const float4*)(cb + (size_t)k * DIM);
    float d = 0.0f;
#pragma unroll
    for (int i = 0; i < 16; i++) {
        float4 a = row[i];
        d = fmaf(a.x, zr[4 * i + 0], d);
        d = fmaf(a.y, zr[4 * i + 1], d);
        d = fmaf(a.z, zr[4 * i + 2], d);
        d = fmaf(a.w, zr[4 * i + 3], d);
    }
    return __fadd_rn(__fsub_rn(zn, __fmul_rn(2.0f, d)), cn);
}

// ---------------------------------------------------------------------------
// Prep 0: codebook row norms (one warp per code) — unchanged from round 3.
// ---------------------------------------------------------------------------
__global__ void cnorm_kernel(const float* __restrict__ cb) {
    int w = (blockIdx.x * blockDim.x + threadIdx.x) >> 5;
    int l = threadIdx.x & 31;
    if (w < NUM_CODES) {
        float2 v = *(const float2*)(cb + (size_t)w * DIM + 2 * l);
        float s = fmaf(v.x, v.x, v.y * v.y);
#pragma unroll
        for (int off = 16; off > 0; off >>= 1)
            s += __shfl_down_sync(0xFFFFFFFFu, s, off);
        if (l == 0) g_cnorm[w] = s;
    }
}

// ---------------------------------------------------------------------------
// Prep 1: codebook -> tf32 B fragments.
// o = ((t*8 + j)*8 + kk)*64 + lane*2 + h ; code=t*64+j*8+(lane>>2),
// dim = kk*8 + (lane&3) + h*4   (m16n8k8 B: b0=(k=tig,n=gid), b1=(k=tig+4,n=gid))
// ---------------------------------------------------------------------------
__global__ void bprep_kernel(const float* __restrict__ cb) {
    int o = blockIdx.x * blockDim.x + threadIdx.x;
    if (o < NUM_CODES * DIM) {
        int h = o & 1, lane = (o >> 1) & 31, kk = (o >> 6) & 7;
        int j = (o >> 9) & 7, t = o >> 12;
        int code = t * 64 + j * 8 + (lane >> 2);
        int dim  = kk * 8 + (lane & 3) + h * 4;
        g_bfrag[o] = f2tf32(cb[(size_t)code * DIM + dim]);
    }
}

// ---------------------------------------------------------------------------
// Prep 2: z -> tf32 A fragments.
// o = (((blk*4 + w)*2 + m)*8 + kk)*128 + lane*4 + r
// a0=(row gid,col tig) a1=(gid+8,tig) a2=(gid,tig+4) a3=(gid+8,tig+4)
// row -> vector = blk*128 + w*32 + m*16 + gid + (r&1)*8
// col -> dim    = kk*8 + tig + (r>>1)*4
// ---------------------------------------------------------------------------
__global__ void zprep_kernel(const float* __restrict__ z) {
    int o = blockIdx.x * blockDim.x + threadIdx.x;
    if (o < N_VEC * DIM) {
        int r = o & 3, lane = (o >> 2) & 31, kk = (o >> 7) & 7;
        int m = (o >> 10) & 1, w = (o >> 11) & 3, blk = o >> 13;
        int vec = blk * 128 + w * 32 + m * 16 + (lane >> 2) + ((r & 1) << 3);
        int dim = kk * 8 + (lane & 3) + ((r >> 1) << 2);
        int b = vec >> 10, hw = vec & (HW - 1);
        g_afrag[o] = f2tf32(z[(size_t)b * DIM * HW + (size_t)dim * HW + hw]);
    }
}

// ---------------------------------------------------------------------------
// Main: mma filter + exact recheck + output + loss partials
// ---------------------------------------------------------------------------
__global__ void __launch_bounds__(TPB, 2)
vq_main_kernel(const float* __restrict__ z,
               const float* __restrict__ cb,
               float* __restrict__ out) {
    extern __shared__ __align__(16) unsigned char smem[];
    uint32_t* s_b  = (uint32_t*)(smem + OFF_B);
    float*    s_d  = (float*)(smem + OFF_D);
    float*    s_cn = (float*)(smem + OFF_CN);
    float*    s_red= (float*)(smem + OFF_RED);

    const int tid  = threadIdx.x;
    const int w    = tid >> 5;
    const int lane = tid & 31;
    const int gid  = lane >> 2, tig = lane & 3;
    const int n    = blockIdx.x * TPB + tid;
    const int b    = n >> 10;
    const int hw   = n & (HW - 1);

    // zn (round-2 sequential order)
    const float* zp = z + (size_t)b * DIM * HW + hw;
    float zn = 0.0f;
#pragma unroll
    for (int c = 0; c < DIM; c++) {
        float v = zp[(size_t)c * HW];
        zn = fmaf(v, v, zn);
    }

    // code norms -> smem
#pragma unroll
    for (int i = 0; i < NUM_CODES / TPB; i++)
        s_cn[tid + i * TPB] = g_cnorm[tid + i * TPB];

    // A fragments: register-resident (coalesced LDG.128)
    uint32_t afr[2][8][4];
    {
        const uint4* ap = (const uint4*)g_afrag + (size_t)(blockIdx.x * 4 + w) * 2 * 8 * 32;
#pragma unroll
        for (int m = 0; m < 2; m++)
#pragma unroll
            for (int kk = 0; kk < 8; kk++) {
                uint4 v = ap[(m * 8 + kk) * 32 + lane];
                afr[m][kk][0] = v.x; afr[m][kk][1] = v.y;
                afr[m][kk][2] = v.z; afr[m][kk][3] = v.w;
            }
    }

    // stage B chunk 0 into buf 0
    const uint4* bsrc = (const uint4*)g_bfrag;
    {
        uint4* bdst = (uint4*)s_b;
#pragma unroll
        for (int i = 0; i < 8; i++) bdst[i * TPB + tid] = bsrc[i * TPB + tid];
    }
    __syncthreads();

    float runmin = 3.402823466e38f, thr = 3.402823466e38f;
    int cand[MAXCAND];
    int cnt = 0;
    float* dw = s_d + w * 32 * DPAD;

#pragma unroll 1
    for (int t = 0; t < NCHUNK; t++) {
        // prefetch next chunk into regs (overlaps mma)
        uint4 pf[8];
        if (t + 1 < NCHUNK) {
#pragma unroll
            for (int i = 0; i < 8; i++)
                pf[i] = bsrc[(t + 1) * 1024 + i * TPB + tid];
        }

        const uint32_t* bbuf = s_b + (t & 1) * 4096;
        // 8 n-tiles x 8 k-steps x 2 m-tiles
#pragma unroll
        for (int j = 0; j < 8; j++) {
            float d0[4] = {0.f, 0.f, 0.f, 0.f}, d1[4] = {0.f, 0.f, 0.f, 0.f};
#pragma unroll
            for (int kk = 0; kk < 8; kk++) {
                uint2 bb = *(const uint2*)&bbuf[((j * 8 + kk) * 32 + lane) * 2];
                mma_tf32(d0, afr[0][kk], bb.x, bb.y);
                mma_tf32(d1, afr[1][kk], bb.x, bb.y);
            }
            // D -> smem (row = vector-in-warp, col = code-in-chunk)
            *(float2*)&dw[(gid +  0) * DPAD + j * 8 + tig * 2] = make_float2(d0[0], d0[1]);
            *(float2*)&dw[(gid +  8) * DPAD + j * 8 + tig * 2] = make_float2(d0[2], d0[3]);
            *(float2*)&dw[(gid + 16) * DPAD + j * 8 + tig * 2] = make_float2(d1[0], d1[1]);
            *(float2*)&dw[(gid + 24) * DPAD + j * 8 + tig * 2] = make_float2(d1[2], d1[3]);
        }
        __syncwarp();

        // serial ascending-k filter on this thread's own row
        const float* drow = dw + lane * DPAD;
        const float* cnp  = s_cn + t * 64;
#pragma unroll
        for (int c4 = 0; c4 < 16; c4++) {
            float4 dd = *(const float4*)&drow[c4 * 4];
            float4 cc = *(const float4*)&cnp[c4 * 4];
            float s0 = fmaf(-2.0f, dd.x, cc.x);
            float s1 = fmaf(-2.0f, dd.y, cc.y);
            float s2 = fmaf(-2.0f, dd.z, cc.z);
            float s3 = fmaf(-2.0f, dd.w, cc.w);
            int kb = t * 64 + c4 * 4;
            if (s0 < thr) { if (cnt < MAXCAND) cand[cnt] = kb + 0; cnt++;
                            if (s0 < runmin) { runmin = s0; thr = runmin + EPS2; } }
            if (s1 < thr) { if (cnt < MAXCAND) cand[cnt] = kb + 1; cnt++;
                            if (s1 < runmin) { runmin = s1; thr = runmin + EPS2; } }
            if (s2 < thr) { if (cnt < MAXCAND) cand[cnt] = kb + 2; cnt++;
                            if (s2 < runmin) { runmin = s2; thr = runmin + EPS2; } }
            if (s3 < thr) { if (cnt < MAXCAND) cand[cnt] = kb + 3; cnt++;
                            if (s3 < runmin) { runmin = s3; thr = runmin + EPS2; } }
        }

        // commit prefetched chunk to the other buffer
        if (t + 1 < NCHUNK) {
            uint4* bdst = (uint4*)(s_b + ((t + 1) & 1) * 4096);
#pragma unroll
            for (int i = 0; i < 8; i++) bdst[i * TPB + tid] = pf[i];
        }
        __syncthreads();
    }

    // exact selection among candidates (ascending k, strict < = first index)
    float zr[DIM];
#pragma unroll
    for (int c = 0; c < DIM; c++) zr[c] = zp[(size_t)c * HW];

    float best = 3.402823466e38f;
    int bestk = 0;
    if (cnt <= MAXCAND) {
        for (int jj = 0; jj < cnt; jj++) {
            int k = cand[jj];
            float s = exact_score(cb, k, zr, zn, s_cn[k]);
            if (s < best) { best = s; bestk = k; }
        }
    } else {  // deterministic fallback (P ~ 0): full exact scan
        for (int k = 0; k < NUM_CODES; k++) {
            float s = exact_score(cb, k, zr, zn, s_cn[k]);
            if (s < best) { best = s; bestk = k; }
        }
    }

    // gather + straight-through output + loss (round-2 identical rounding)
    const float* crow = cb + (size_t)bestk * DIM;
    float* op = out + (size_t)b * DIM * HW + hw;
    float lsum = 0.0f;
#pragma unroll
    for (int c = 0; c < DIM; c++) {
        float q = crow[c];
        float d = __fsub_rn(q, zr[c]);
        lsum = fmaf(d, d, lsum);
        op[(size_t)c * HW] = __fadd_rn(zr[c], d);
    }

    __syncthreads();
    s_red[tid] = lsum;
    __syncthreads();
#pragma unroll
    for (int s = TPB / 2; s > 0; s >>= 1) {
        if (tid < s) s_red[tid] += s_red[tid + s];
        __syncthreads();
    }
    if (tid == 0) g_partial[blockIdx.x] = s_red[0];
}

// ---------------------------------------------------------------------------
__global__ void loss_kernel(float* __restrict__ loss_out) {
    __shared__ float s_red[NBLOCKS];
    int tid = threadIdx.x;
    s_red[tid] = g_partial[tid];
    __syncthreads();
#pragma unroll
    for (int s = NBLOCKS / 2; s > 0; s >>= 1) {
        if (tid < s) s_red[tid] += s_red[tid + s];
        __syncthreads();
    }
    if (tid == 0) loss_out[0] = s_red[0] * (1.25f / (float)N_TOTAL);
}

// ---------------------------------------------------------------------------
extern "C" void kernel_launch(void* const* d_in, const int* in_sizes, int n_in,
                              void* d_out, int out_size) {
    const float* z  = (const float*)d_in[0];
    const float* cb = (const float*)d_in[1];
    float* out = (float*)d_out;

    cudaFuncSetAttribute(vq_main_kernel,
                         cudaFuncAttributeMaxDynamicSharedMemorySize, SMEM_TOTAL);

    cnorm_kernel<<<NUM_CODES * 32 / 256, 256>>>(cb);
    bprep_kernel<<<NUM_CODES * DIM / 256, 256>>>(cb);
    zprep_kernel<<<N_VEC * DIM / 256, 256>>>(z);
    vq_main_kernel<<<NBLOCKS, TPB, SMEM_TOTAL>>>(z, cb, out);
    if (out_size > N_TOTAL) {
        loss_kernel<<<1, NBLOCKS>>>(out + (out_size - 1));
    }
}